// round 8
// baseline (speedup 1.0000x reference)
#include <cuda_runtime.h>
#include <cstdint>

#define B_  4096
#define PIT 104

__device__ unsigned g_amax[16];
__device__ float    g_wscale[8];
__device__ float    g_wthr[8];
__device__ float    g_actX0[B_*16*64];
__device__ float    g_actX [B_*128*64];
__device__ float    g_actY [B_*128*64];
__device__ uint2    g_ent[5*128*1152];
__device__ int      g_entcnt[5*128];
__device__ int8_t   g_wfc1c[8192*64];
__device__ float    g_wsrcv[64*64];
__device__ float    g_woutv[64*64];
__device__ float    g_fc1[B_*64];
__device__ float    g_srcb[B_*64];
__device__ float    g_merge[B_*64];
__device__ float    g_mq[B_*64];
__device__ float    g_sig[B_*64];
__device__ float    g_mean[64];
__device__ float    g_var[64];

__device__ __forceinline__ void warp_amax_commit(float v, int slot) {
    #pragma unroll
    for (int o = 16; o; o >>= 1) v = fmaxf(v, __shfl_xor_sync(0xffffffffu, v, o));
    if ((threadIdx.x & 31) == 0) atomicMax(&g_amax[slot], __float_as_uint(v));
}

// XLA f32 tanh rational polynomial
__device__ __forceinline__ float xla_tanh(float x) {
    float ax = fabsf(x);
    float xc = fminf(fmaxf(x, -7.90531110763549805f), 7.90531110763549805f);
    float x2 = __fmul_rn(xc, xc);
    float p = -2.76076847742355e-16f;
    p = fmaf(p, x2, 2.00018790482477e-13f);
    p = fmaf(p, x2, -8.60467152213735e-11f);
    p = fmaf(p, x2, 5.12229709037114e-08f);
    p = fmaf(p, x2, 1.48572235717979e-05f);
    p = fmaf(p, x2, 6.37261928875436e-04f);
    p = fmaf(p, x2, 4.89352455891786e-03f);
    float num = __fmul_rn(xc, p);
    float q = 1.19825839466702e-06f;
    q = fmaf(q, x2, 1.18534705686654e-04f);
    q = fmaf(q, x2, 2.26843463243900e-03f);
    q = fmaf(q, x2, 4.89352518554385e-03f);
    float r = __fdiv_rn(num, q);
    return (ax < 0.0004f) ? x : r;
}

__global__ void k_zero_scalars() { if (threadIdx.x < 16) g_amax[threadIdx.x] = 0u; }

__global__ void k_wsel(const float* __restrict__ w, int n, int keep, int widx) {
    __shared__ unsigned hist[256];
    __shared__ unsigned sh_prefix, sh_krem, sh_amax;
    const int tid = threadIdx.x;
    if (tid == 0) { sh_prefix = 0u; sh_krem = (unsigned)keep; sh_amax = 0u; }
    __syncthreads();
    unsigned mymax = 0u;
    for (int i = tid; i < n; i += blockDim.x)
        mymax = max(mymax, __float_as_uint(fabsf(w[i])));
    atomicMax(&sh_amax, mymax);
    __syncthreads();
    for (int shift = 24; shift >= 0; shift -= 8) {
        for (int j = tid; j < 256; j += blockDim.x) hist[j] = 0u;
        __syncthreads();
        const unsigned prefix = sh_prefix;
        for (int i = tid; i < n; i += blockDim.x) {
            unsigned key = __float_as_uint(fabsf(w[i]));
            if (shift == 24 || (key >> (shift + 8)) == prefix)
                atomicAdd(&hist[(key >> shift) & 255u], 1u);
        }
        __syncthreads();
        if (tid == 0) {
            unsigned krem = sh_krem, cum = 0u; int d = 0;
            for (int b = 255; b >= 0; --b) {
                unsigned c = hist[b];
                if (cum + c >= krem) { d = b; sh_krem = krem - cum; break; }
                cum += c;
            }
            sh_prefix = (prefix << 8) | (unsigned)d;
        }
        __syncthreads();
    }
    if (tid == 0) {
        g_wthr[widx]   = __uint_as_float(sh_prefix);
        g_wscale[widx] = __fadd_rn(__fdiv_rn(__uint_as_float(sh_amax), 7.0f), 1e-8f);
    }
}

// sparse per-cout entries, (kh, kw, ci) ascending (Eigen patch order)
__global__ void k_went(const float* __restrict__ w, int layer, int cin) {
    int co = threadIdx.x;
    float thr = g_wthr[layer], s = g_wscale[layer];
    uint2* el = g_ent + (layer * 128 + co) * 1152;
    int n = 0;
    for (int kh = 0; kh < 3; ++kh)
        for (int kw = 0; kw < 3; ++kw)
            for (int ci = 0; ci < cin; ++ci) {
                float v = w[(co * cin + ci) * 9 + kh * 3 + kw];
                if (fabsf(v) >= thr) {
                    float q = fminf(fmaxf(rintf(__fdiv_rn(v, s)), -8.f), 7.f);
                    if (q != 0.f) {
                        el[n].x = (unsigned)(ci * PIT + kh * 10 + kw);
                        el[n].y = __float_as_uint(__fmul_rn(q, s));
                        n++;
                    }
                }
            }
    g_entcnt[layer * 128 + co] = n;
}

__global__ void k_wamax_lin(const float* __restrict__ w, int n, int sidx) {
    __shared__ unsigned sm;
    if (threadIdx.x == 0) sm = 0u;
    __syncthreads();
    float m = 0.0f;
    for (int i = threadIdx.x; i < n; i += blockDim.x) m = fmaxf(m, fabsf(w[i]));
    atomicMax(&sm, __float_as_uint(m));
    __syncthreads();
    if (threadIdx.x == 0)
        g_wscale[sidx] = __fadd_rn(__fdiv_rn(__uint_as_float(sm), 7.0f), 1e-8f);
}

__global__ void k_wfc1c(const float* __restrict__ w) {
    int idx = blockIdx.x * blockDim.x + threadIdx.x;
    if (idx >= 64 * 8192) return;
    int o = idx >> 13, k = idx & 8191;
    float s = g_wscale[5];
    float q = fminf(fmaxf(rintf(__fdiv_rn(w[idx], s)), -8.f), 7.f);
    g_wfc1c[k * 64 + o] = (int8_t)q;
}

__global__ void k_wlin_smallT(const float* __restrict__ w, int which) {
    __shared__ unsigned sm;
    if (threadIdx.x == 0) sm = 0u;
    __syncthreads();
    float m = 0.0f;
    for (int i = threadIdx.x; i < 4096; i += blockDim.x) m = fmaxf(m, fabsf(w[i]));
    atomicMax(&sm, __float_as_uint(m));
    __syncthreads();
    float s = __fadd_rn(__fdiv_rn(__uint_as_float(sm), 7.0f), 1e-8f);
    float* dst = which ? g_woutv : g_wsrcv;
    for (int i = threadIdx.x; i < 4096; i += blockDim.x) {
        int o = i >> 6, j = i & 63;
        float q = fminf(fmaxf(rintf(__fdiv_rn(w[i], s)), -8.f), 7.f);
        dst[j * 64 + o] = __fmul_rn(q, s);
    }
}

__global__ void k_amax_abs(const float* __restrict__ x, int n, int slot) {
    float m = 0.0f;
    for (int i = blockIdx.x * blockDim.x + threadIdx.x; i < n; i += gridDim.x * blockDim.x)
        m = fmaxf(m, fabsf(x[i]));
    warp_amax_commit(m, slot);
}

__global__ void k_prep0(const float* __restrict__ cb) {
    int i = blockIdx.x * blockDim.x + threadIdx.x;
    if (i >= B_ * 16 * 64) return;
    int pix = i & 63, ci = (i >> 6) & 15, img = i >> 10;
    float xv = 0.f;
    if (ci < 12) {
        float s0 = __fadd_rn(__fdiv_rn(__uint_as_float(g_amax[0]), 7.0f), 1e-8f);
        float v = cb[(img * 12 + ci) * 64 + pix];
        float c = fminf(fmaxf(rintf(__fdiv_rn(v, s0)), -8.f), 7.f);
        xv = __fmul_rn(c, s0);
    }
    g_actX0[i] = xv;
}

// relu out -> next input values. mode1: fq_signed(qrelu(v)); mode0: qrelu(v)
__global__ void k_quantU(int slot, int mode) {
    float amax = __uint_as_float(g_amax[slot]);
    float su = __fadd_rn(__fdiv_rn(amax, 15.f), 1e-8f);
    float sx = 1.f;
    if (mode) {
        float mu = fminf(fmaxf(rintf(__fdiv_rn(amax, su)), 0.f), 15.f);
        sx = __fadd_rn(__fdiv_rn(__fmul_rn(mu, su), 7.f), 1e-8f);
    }
    const int n = B_ * 128 * 64;
    for (int i = blockIdx.x * blockDim.x + threadIdx.x; i < n; i += gridDim.x * blockDim.x) {
        float v = g_actY[i];
        float q = fminf(fmaxf(rintf(__fdiv_rn(v, su)), 0.f), 15.f);
        float vq = __fmul_rn(q, su);
        float outv = vq;
        if (mode) {
            float c = fminf(fmaxf(rintf(__fdiv_rn(vq, sx)), -8.f), 7.f);
            outv = __fmul_rn(c, sx);
        }
        g_actX[i] = outv;
    }
}

// sparse sequential-FMA conv. CTA=(img, 32-co group), 256 thr = 64 pix x 4 co
template<int CIN_T>
__global__ void __launch_bounds__(256) k_conv(const float* __restrict__ in,
                                              const float* __restrict__ bias,
                                              const uint2* __restrict__ ent,
                                              const int* __restrict__ ecnt,
                                              int outslot) {
    extern __shared__ float sT[];
    const int img = blockIdx.x, cog = blockIdx.y;
    const int tid = threadIdx.x;
    for (int i = tid; i < CIN_T * PIT; i += 256) sT[i] = 0.f;
    __syncthreads();
    const float* src = in + (size_t)img * CIN_T * 64;
    for (int i = tid; i < CIN_T * 64; i += 256) {
        int ci = i >> 6, p = i & 63;
        sT[ci * PIT + (p >> 3) * 10 + (p & 7) + 11] = src[i];
    }
    __syncthreads();

    const int pix = tid & 63, colane = tid >> 6;
    const int basep = (pix >> 3) * 10 + (pix & 7);
    float lmax = 0.f;

    #pragma unroll 1
    for (int it = 0; it < 8; ++it) {
        const int co = cog * 32 + it * 4 + colane;
        const uint2* el = ent + co * 1152;
        const int n = ecnt[co];
        float acc = 0.f;
        int e = 0;
        #pragma unroll 1
        for (; e + 4 <= n; e += 4) {
            uint2 u0 = __ldg(&el[e]);
            uint2 u1 = __ldg(&el[e + 1]);
            uint2 u2 = __ldg(&el[e + 2]);
            uint2 u3 = __ldg(&el[e + 3]);
            acc = fmaf(sT[basep + u0.x], __uint_as_float(u0.y), acc);
            acc = fmaf(sT[basep + u1.x], __uint_as_float(u1.y), acc);
            acc = fmaf(sT[basep + u2.x], __uint_as_float(u2.y), acc);
            acc = fmaf(sT[basep + u3.x], __uint_as_float(u3.y), acc);
        }
        for (; e < n; ++e) {
            uint2 u = __ldg(&el[e]);
            acc = fmaf(sT[basep + u.x], __uint_as_float(u.y), acc);
        }
        float y = __fadd_rn(acc, __ldg(&bias[co]));
        y = fmaxf(y, 0.f);
        lmax = fmaxf(lmax, y);
        g_actY[((size_t)img * 128 + co) * 64 + pix] = y;
    }
    warp_amax_commit(lmax, outslot);
}

// fc1: sequential ascending k (= c*64+pix flatten order)
__global__ void __launch_bounds__(256) k_fc1(const float* __restrict__ bias) {
    extern __shared__ char smc[];
    int8_t* swc = (int8_t*)smc;               // [1024][64]
    float*  sxv = (float*)(smc + 65536);      // [4][1024]
    const int tid = threadIdx.x;
    const int o = tid & 63, il = tid >> 6;
    const int img0 = blockIdx.x * 4;
    const float sw = g_wscale[5];
    float acc = 0.f;
    #pragma unroll 1
    for (int ch = 0; ch < 8; ++ch) {
        __syncthreads();
        const int4* ws4 = (const int4*)(g_wfc1c + ch * 1024 * 64);
        int4* wd4 = (int4*)swc;
        for (int i = tid; i < 4096; i += 256) wd4[i] = ws4[i];
        for (int i = tid; i < 4096; i += 256) {
            int ill = i >> 10, kk = i & 1023;
            sxv[i] = g_actX[(size_t)(img0 + ill) * 8192 + ch * 1024 + kk];
        }
        __syncthreads();
        const float* xr = sxv + il * 1024;
        #pragma unroll 4
        for (int kk = 0; kk < 1024; ++kk) {
            float wv = __fmul_rn((float)swc[kk * 64 + o], sw);
            acc = fmaf(xr[kk], wv, acc);
        }
    }
    float y = __fadd_rn(acc, __ldg(&bias[o]));
    g_fc1[(size_t)(img0 + il) * 64 + o] = y;
    warp_amax_commit(fabsf(y), 6);
}

__global__ void __launch_bounds__(256) k_src(const float* __restrict__ x,
                                             const float* __restrict__ bias) {
    __shared__ float sw[64 * 64];
    const int tid = threadIdx.x;
    for (int i = tid; i < 4096; i += 256) sw[i] = g_wsrcv[i];
    __syncthreads();
    const int o = tid & 63, il = tid >> 6;
    const int img = blockIdx.x * 4 + il;
    const float* xr = x + (size_t)img * 64;
    float acc = 0.f;
    #pragma unroll 1
    for (int j = 0; j < 64; ++j)
        acc = fmaf(__ldg(&xr[j]), sw[j * 64 + o], acc);
    float y = __fadd_rn(acc, __ldg(&bias[o]));
    g_srcb[(size_t)img * 64 + o] = y;
    warp_amax_commit(fabsf(y), 7);
}

__global__ void k_merge() {
    int i = blockIdx.x * blockDim.x + threadIdx.x;
    if (i >= B_ * 64) return;
    float s6 = __fadd_rn(__fdiv_rn(__uint_as_float(g_amax[6]), 7.f), 1e-8f);
    float s7 = __fadd_rn(__fdiv_rn(__uint_as_float(g_amax[7]), 7.f), 1e-8f);
    float a = __fmul_rn(fminf(fmaxf(rintf(__fdiv_rn(g_fc1[i], s6)), -8.f), 7.f), s6);
    float c = __fmul_rn(fminf(fmaxf(rintf(__fdiv_rn(g_srcb[i], s7)), -8.f), 7.f), s7);
    g_merge[i] = __fadd_rn(a, c);
}

__global__ void k_bnstats() {
    int c = threadIdx.x;                      // 64 threads, sequential rows
    float s = 0.f;
    for (int r = 0; r < B_; ++r) s = __fadd_rn(s, g_merge[r * 64 + c]);
    float m = __fdiv_rn(s, 4096.f);
    g_mean[c] = m;
    float v = 0.f;
    for (int r = 0; r < B_; ++r) {
        float d = __fadd_rn(g_merge[r * 64 + c], -m);
        v = __fadd_rn(v, __fmul_rn(d, d));
    }
    g_var[c] = __fdiv_rn(v, 4096.f);
}

__global__ void k_bnrelu(const float* __restrict__ gamma, const float* __restrict__ beta) {
    int i = blockIdx.x * blockDim.x + threadIdx.x;
    if (i >= B_ * 64) return;
    int c = i & 63;
    float ve = __fadd_rn(g_var[c], 1e-5f);
    float r1 = __fdiv_rn(1.0f, __fsqrt_rn(ve));
    float d  = __fadd_rn(g_merge[i], -g_mean[c]);
    float t  = __fadd_rn(__fmul_rn(__fmul_rn(gamma[c], d), r1), beta[c]);
    float r  = fmaxf(t, 0.0f);
    g_merge[i] = r;
    warp_amax_commit(r, 8);
}

__global__ void k_mq() {
    int i = blockIdx.x * blockDim.x + threadIdx.x;
    if (i >= B_ * 64) return;
    float s = __fadd_rn(__fdiv_rn(__uint_as_float(g_amax[8]), 15.f), 1e-8f);
    float q = fminf(fmaxf(rintf(__fdiv_rn(g_merge[i], s)), 0.f), 15.f);
    g_mq[i] = __fmul_rn(q, s);
}

__global__ void __launch_bounds__(256) k_out(const float* __restrict__ bias) {
    __shared__ float sw[64 * 64];
    const int tid = threadIdx.x;
    for (int i = tid; i < 4096; i += 256) sw[i] = g_woutv[i];
    __syncthreads();
    const int o = tid & 63, il = tid >> 6;
    const int img = blockIdx.x * 4 + il;
    const float* xr = g_mq + (size_t)img * 64;
    float acc = 0.f;
    #pragma unroll 1
    for (int j = 0; j < 64; ++j)
        acc = fmaf(xr[j], sw[j * 64 + o], acc);
    float y = __fadd_rn(acc, __ldg(&bias[o]));
    // XLA logistic: 0.5*tanh(0.5*x) + 0.5
    float t = xla_tanh(__fmul_rn(0.5f, y));
    float sig = __fadd_rn(__fmul_rn(0.5f, t), 0.5f);
    g_sig[(size_t)img * 64 + o] = sig;
    warp_amax_commit(sig, 9);
}

__global__ void k_final(float* __restrict__ out) {
    int i = blockIdx.x * blockDim.x + threadIdx.x;
    if (i >= B_ * 64) return;
    float s = __fadd_rn(__fdiv_rn(__uint_as_float(g_amax[9]), 15.f), 1e-8f);
    float q = fminf(fmaxf(rintf(__fdiv_rn(g_sig[i], s)), 0.f), 15.f);
    out[i] = __fmul_rn(q, s);
}

extern "C" void kernel_launch(void* const* d_in, const int* in_sizes, int n_in,
                              void* d_out, int out_size) {
    const float* cb    = (const float*)d_in[0];
    const float* srcx  = (const float*)d_in[1];
    const float* wconv[5] = {(const float*)d_in[2], (const float*)d_in[4],
                             (const float*)d_in[6], (const float*)d_in[8],
                             (const float*)d_in[10]};
    const float* bconv[5] = {(const float*)d_in[3], (const float*)d_in[5],
                             (const float*)d_in[7], (const float*)d_in[9],
                             (const float*)d_in[11]};
    const float* wfc1  = (const float*)d_in[12];
    const float* bfc1  = (const float*)d_in[13];
    const float* wsrc  = (const float*)d_in[14];
    const float* bsrc  = (const float*)d_in[15];
    const float* gamma = (const float*)d_in[16];
    const float* beta  = (const float*)d_in[17];
    const float* wout  = (const float*)d_in[18];
    const float* bout  = (const float*)d_in[19];
    float* outp = (float*)d_out;

    const int SMC128 = 128 * PIT * 4;   // 53248
    const int SMC16  = 16 * PIT * 4;    // 6656
    const int SMFC1  = 65536 + 16384;   // 81920
    cudaFuncSetAttribute((const void*)k_conv<128>,
                         cudaFuncAttributeMaxDynamicSharedMemorySize, SMC128);
    cudaFuncSetAttribute((const void*)k_conv<16>,
                         cudaFuncAttributeMaxDynamicSharedMemorySize, SMC16);
    cudaFuncSetAttribute((const void*)k_fc1,
                         cudaFuncAttributeMaxDynamicSharedMemorySize, SMFC1);

    k_zero_scalars<<<1, 32>>>();

    const int cins[5] = {12, 128, 128, 128, 128};
    for (int i = 0; i < 5; i++) {
        k_wsel<<<1, 1024>>>(wconv[i], 128 * cins[i] * 9, 84 * 128, i);
        k_went<<<1, 128>>>(wconv[i], i, cins[i]);
    }
    k_wamax_lin<<<1, 1024>>>(wfc1, 64 * 8192, 5);
    k_wfc1c<<<(64 * 8192 + 255) / 256, 256>>>(wfc1);
    k_wlin_smallT<<<1, 1024>>>(wsrc, 0);
    k_wlin_smallT<<<1, 1024>>>(wout, 1);

    k_amax_abs<<<2048, 256>>>(cb, B_ * 12 * 64, 0);
    k_prep0<<<(B_ * 16 * 64 + 255) / 256, 256>>>(cb);

    float* x0p = nullptr; float* xp = nullptr;
    uint2* entp = nullptr; int* ecp = nullptr;
    cudaGetSymbolAddress((void**)&x0p, g_actX0);
    cudaGetSymbolAddress((void**)&xp, g_actX);
    cudaGetSymbolAddress((void**)&entp, g_ent);
    cudaGetSymbolAddress((void**)&ecp, g_entcnt);

    dim3 cgrid(B_, 4);
    k_conv<16><<<cgrid, 256, SMC16>>>(x0p, bconv[0], entp, ecp, 1);
    for (int b = 1; b < 5; b++) {
        k_quantU<<<4096, 256>>>(b, 1);
        k_conv<128><<<cgrid, 256, SMC128>>>(xp, bconv[b],
                                            entp + b * 128 * 1152, ecp + b * 128, b + 1);
    }
    k_quantU<<<4096, 256>>>(5, 0);

    k_fc1<<<B_ / 4, 256, SMFC1>>>(bfc1);
    k_src<<<B_ / 4, 256>>>(srcx, bsrc);
    k_merge<<<(B_ * 64 + 255) / 256, 256>>>();
    k_bnstats<<<1, 64>>>();
    k_bnrelu<<<(B_ * 64 + 255) / 256, 256>>>(gamma, beta);
    k_mq<<<(B_ * 64 + 255) / 256, 256>>>();
    k_out<<<B_ / 4, 256>>>(bout);
    k_final<<<(B_ * 64 + 255) / 256, 256>>>(outp);
    (void)in_sizes; (void)n_in; (void)out_size;
}

// round 9
// speedup vs baseline: 1.3171x; 1.3171x over previous
#include <cuda_runtime.h>
#include <cstdint>

#define B_  4096
#define PIT 104

__device__ unsigned g_amax[16];
__device__ float    g_wscale[8];
__device__ float    g_wthr[8];
__device__ float    g_actX0[B_*16*64];
__device__ float    g_actX [B_*128*64];
__device__ float    g_actY [B_*128*64];
__device__ uint2    g_ent[5*128*1152];
__device__ int      g_entcnt[5*128];      // uint4-group count per co
__device__ int8_t   g_wfc1c[8192*64];
__device__ float    g_wsrcv[64*64];
__device__ float    g_woutv[64*64];
__device__ float    g_fc1[B_*64];
__device__ float    g_srcb[B_*64];
__device__ float    g_merge[B_*64];
__device__ float    g_mq[B_*64];
__device__ float    g_sig[B_*64];
__device__ float    g_mean[64];
__device__ float    g_var[64];

struct WP { const float* w[5]; int n[5]; int cin[5]; };

__device__ __forceinline__ void warp_amax_commit(float v, int slot) {
    #pragma unroll
    for (int o = 16; o; o >>= 1) v = fmaxf(v, __shfl_xor_sync(0xffffffffu, v, o));
    if ((threadIdx.x & 31) == 0) atomicMax(&g_amax[slot], __float_as_uint(v));
}

__device__ __forceinline__ float xla_tanh(float x) {
    float ax = fabsf(x);
    float xc = fminf(fmaxf(x, -7.90531110763549805f), 7.90531110763549805f);
    float x2 = __fmul_rn(xc, xc);
    float p = -2.76076847742355e-16f;
    p = fmaf(p, x2, 2.00018790482477e-13f);
    p = fmaf(p, x2, -8.60467152213735e-11f);
    p = fmaf(p, x2, 5.12229709037114e-08f);
    p = fmaf(p, x2, 1.48572235717979e-05f);
    p = fmaf(p, x2, 6.37261928875436e-04f);
    p = fmaf(p, x2, 4.89352455891786e-03f);
    float num = __fmul_rn(xc, p);
    float q = 1.19825839466702e-06f;
    q = fmaf(q, x2, 1.18534705686654e-04f);
    q = fmaf(q, x2, 2.26843463243900e-03f);
    q = fmaf(q, x2, 4.89352518554385e-03f);
    float r = __fdiv_rn(num, q);
    return (ax < 0.0004f) ? x : r;
}

__global__ void k_zero_scalars() { if (threadIdx.x < 16) g_amax[threadIdx.x] = 0u; }

// 5 layers in parallel: blockIdx.x = layer
__global__ void k_wsel5(WP wp, int keep) {
    const int L = blockIdx.x;
    const float* __restrict__ w = wp.w[L];
    const int n = wp.n[L];
    __shared__ unsigned hist[256];
    __shared__ unsigned sh_prefix, sh_krem, sh_amax;
    const int tid = threadIdx.x;
    if (tid == 0) { sh_prefix = 0u; sh_krem = (unsigned)keep; sh_amax = 0u; }
    __syncthreads();
    unsigned mymax = 0u;
    for (int i = tid; i < n; i += blockDim.x)
        mymax = max(mymax, __float_as_uint(fabsf(w[i])));
    atomicMax(&sh_amax, mymax);
    __syncthreads();
    for (int shift = 24; shift >= 0; shift -= 8) {
        for (int j = tid; j < 256; j += blockDim.x) hist[j] = 0u;
        __syncthreads();
        const unsigned prefix = sh_prefix;
        for (int i = tid; i < n; i += blockDim.x) {
            unsigned key = __float_as_uint(fabsf(w[i]));
            if (shift == 24 || (key >> (shift + 8)) == prefix)
                atomicAdd(&hist[(key >> shift) & 255u], 1u);
        }
        __syncthreads();
        if (tid == 0) {
            unsigned krem = sh_krem, cum = 0u; int d = 0;
            for (int b = 255; b >= 0; --b) {
                unsigned c = hist[b];
                if (cum + c >= krem) { d = b; sh_krem = krem - cum; break; }
                cum += c;
            }
            sh_prefix = (prefix << 8) | (unsigned)d;
        }
        __syncthreads();
    }
    if (tid == 0) {
        g_wthr[L]   = __uint_as_float(sh_prefix);
        g_wscale[L] = __fadd_rn(__fdiv_rn(__uint_as_float(sh_amax), 7.0f), 1e-8f);
    }
}

// sparse entries, (kh,kw,ci) ascending; u.x = float2 byte offset; zero-padded to even
__global__ void k_went5(WP wp) {
    const int L = blockIdx.x, co = threadIdx.x;
    const float* __restrict__ w = wp.w[L];
    const int cin = wp.cin[L];
    float thr = g_wthr[L], s = g_wscale[L];
    uint2* el = g_ent + ((size_t)L * 128 + co) * 1152;
    int n = 0;
    for (int kh = 0; kh < 3; ++kh)
        for (int kw = 0; kw < 3; ++kw)
            for (int ci = 0; ci < cin; ++ci) {
                float v = w[(co * cin + ci) * 9 + kh * 3 + kw];
                if (fabsf(v) >= thr) {
                    float q = fminf(fmaxf(rintf(__fdiv_rn(v, s)), -8.f), 7.f);
                    if (q != 0.f) {
                        el[n].x = (unsigned)((ci * PIT + kh * 10 + kw) * 8);
                        el[n].y = __float_as_uint(__fmul_rn(q, s));
                        n++;
                    }
                }
            }
    if (n & 1) { el[n].x = 0u; el[n].y = 0u; n++; }   // fma(x,+0,acc)==acc exactly
    g_entcnt[L * 128 + co] = n >> 1;                  // uint4 groups
}

__global__ void k_wamax_lin(const float* __restrict__ w, int n, int sidx) {
    __shared__ unsigned sm;
    if (threadIdx.x == 0) sm = 0u;
    __syncthreads();
    float m = 0.0f;
    for (int i = threadIdx.x; i < n; i += blockDim.x) m = fmaxf(m, fabsf(w[i]));
    atomicMax(&sm, __float_as_uint(m));
    __syncthreads();
    if (threadIdx.x == 0)
        g_wscale[sidx] = __fadd_rn(__fdiv_rn(__uint_as_float(sm), 7.0f), 1e-8f);
}

__global__ void k_wfc1c(const float* __restrict__ w) {
    int idx = blockIdx.x * blockDim.x + threadIdx.x;
    if (idx >= 64 * 8192) return;
    int o = idx >> 13, k = idx & 8191;
    float s = g_wscale[5];
    float q = fminf(fmaxf(rintf(__fdiv_rn(w[idx], s)), -8.f), 7.f);
    g_wfc1c[k * 64 + o] = (int8_t)q;
}

__global__ void k_wlin_smallT(const float* __restrict__ w, int which) {
    __shared__ unsigned sm;
    if (threadIdx.x == 0) sm = 0u;
    __syncthreads();
    float m = 0.0f;
    for (int i = threadIdx.x; i < 4096; i += blockDim.x) m = fmaxf(m, fabsf(w[i]));
    atomicMax(&sm, __float_as_uint(m));
    __syncthreads();
    float s = __fadd_rn(__fdiv_rn(__uint_as_float(sm), 7.0f), 1e-8f);
    float* dst = which ? g_woutv : g_wsrcv;
    for (int i = threadIdx.x; i < 4096; i += blockDim.x) {
        int o = i >> 6, j = i & 63;
        float q = fminf(fmaxf(rintf(__fdiv_rn(w[i], s)), -8.f), 7.f);
        dst[j * 64 + o] = __fmul_rn(q, s);
    }
}

__global__ void k_amax_abs(const float* __restrict__ x, int n, int slot) {
    float m = 0.0f;
    for (int i = blockIdx.x * blockDim.x + threadIdx.x; i < n; i += gridDim.x * blockDim.x)
        m = fmaxf(m, fabsf(x[i]));
    warp_amax_commit(m, slot);
}

__global__ void k_prep0(const float* __restrict__ cb) {
    int i = blockIdx.x * blockDim.x + threadIdx.x;
    if (i >= B_ * 16 * 64) return;
    int pix = i & 63, ci = (i >> 6) & 15, img = i >> 10;
    float xv = 0.f;
    if (ci < 12) {
        float s0 = __fadd_rn(__fdiv_rn(__uint_as_float(g_amax[0]), 7.0f), 1e-8f);
        float v = cb[(img * 12 + ci) * 64 + pix];
        float c = fminf(fmaxf(rintf(__fdiv_rn(v, s0)), -8.f), 7.f);
        xv = __fmul_rn(c, s0);
    }
    g_actX0[i] = xv;
}

// relu out -> next input values (float4 vectorized, same scalar math)
__global__ void k_quantU(int slot, int mode) {
    float amax = __uint_as_float(g_amax[slot]);
    float su = __fadd_rn(__fdiv_rn(amax, 15.f), 1e-8f);
    float sx = 1.f;
    if (mode) {
        float mu = fminf(fmaxf(rintf(__fdiv_rn(amax, su)), 0.f), 15.f);
        sx = __fadd_rn(__fdiv_rn(__fmul_rn(mu, su), 7.f), 1e-8f);
    }
    const int n4 = B_ * 128 * 64 / 4;
    const float4* Y4 = (const float4*)g_actY;
    float4* X4 = (float4*)g_actX;
    for (int i = blockIdx.x * blockDim.x + threadIdx.x; i < n4; i += gridDim.x * blockDim.x) {
        float4 v = Y4[i], o;
        float* vp = &v.x; float* op = &o.x;
        #pragma unroll
        for (int j = 0; j < 4; j++) {
            float q = fminf(fmaxf(rintf(__fdiv_rn(vp[j], su)), 0.f), 15.f);
            float vq = __fmul_rn(q, su);
            float outv = vq;
            if (mode) {
                float c = fminf(fmaxf(rintf(__fdiv_rn(vq, sx)), -8.f), 7.f);
                outv = __fmul_rn(c, sx);
            }
            op[j] = outv;
        }
        X4[i] = o;
    }
}

// ---------------------------------------------------------------------------
// Conv: 2 images/CTA, interleaved float2 tiles, LDS.64 serves both images.
// 256 thr = 4 colanes x 2 warps x 32 lanes; warp rows {0,1,4,5}/{2,3,6,7}
// (bank-optimal 2-phase LDS.64). Per-output FMA order == entry order (Eigen).
// ---------------------------------------------------------------------------
template<int CIN_T>
__global__ void __launch_bounds__(256) k_conv(const float* __restrict__ in,
                                              const float* __restrict__ bias,
                                              const uint2* __restrict__ ent,
                                              const int* __restrict__ ecnt,
                                              int outslot) {
    extern __shared__ float sT[];              // CIN_T*104*2 floats, imgA/imgB interleaved
    const int tid = threadIdx.x;
    const size_t imgA = (size_t)blockIdx.x * 2;
    float4* z4 = (float4*)sT;
    for (int i = tid; i < CIN_T * 104 / 2; i += 256) z4[i] = make_float4(0.f, 0.f, 0.f, 0.f);
    __syncthreads();
    const float* inA = in + imgA * CIN_T * 64;
    const float* inB = inA + CIN_T * 64;
    for (int i = tid; i < CIN_T * 64; i += 256) {
        int ci = i >> 6, p = i & 63;
        int o2 = (ci * PIT + (p >> 3) * 10 + (p & 7) + 11) * 2;
        sT[o2]     = inA[i];
        sT[o2 + 1] = inB[i];
    }
    __syncthreads();

    const int lane = tid & 31, w = (tid >> 5) & 1, colane = tid >> 6;
    const int rg = lane >> 3, c = lane & 7;
    const int r = rg + (rg & 2) + 2 * w;       // {0,1,4,5} or {2,3,6,7}
    const int pix = r * 8 + c;
    const char* base = (const char*)sT + (size_t)(r * 10 + c) * 8;
    float lmax = 0.f;

    #pragma unroll 1
    for (int it = 0; it < 32; ++it) {
        const int co = colane * 32 + it;
        const uint4* el = (const uint4*)(ent + (size_t)co * 1152);
        const int ng = ecnt[co];
        float a0 = 0.f, a1 = 0.f;
        #pragma unroll 2
        for (int g = 0; g < ng; ++g) {
            uint4 u = __ldg(&el[g]);
            float2 xa = *(const float2*)(base + u.x);
            float2 xb = *(const float2*)(base + u.z);
            a0 = fmaf(xa.x, __uint_as_float(u.y), a0);
            a1 = fmaf(xa.y, __uint_as_float(u.y), a1);
            a0 = fmaf(xb.x, __uint_as_float(u.w), a0);
            a1 = fmaf(xb.y, __uint_as_float(u.w), a1);
        }
        float bv = __ldg(&bias[co]);
        float y0 = fmaxf(__fadd_rn(a0, bv), 0.f);
        float y1 = fmaxf(__fadd_rn(a1, bv), 0.f);
        lmax = fmaxf(lmax, fmaxf(y0, y1));
        g_actY[(imgA * 128 + co) * 64 + pix] = y0;
        g_actY[((imgA + 1) * 128 + co) * 64 + pix] = y1;
    }
    warp_amax_commit(lmax, outslot);
}

// fc1: sequential ascending k, unchanged numerics
__global__ void __launch_bounds__(256) k_fc1(const float* __restrict__ bias) {
    extern __shared__ char smc[];
    int8_t* swc = (int8_t*)smc;
    float*  sxv = (float*)(smc + 65536);
    const int tid = threadIdx.x;
    const int o = tid & 63, il = tid >> 6;
    const int img0 = blockIdx.x * 4;
    const float sw = g_wscale[5];
    float acc = 0.f;
    #pragma unroll 1
    for (int ch = 0; ch < 8; ++ch) {
        __syncthreads();
        const int4* ws4 = (const int4*)(g_wfc1c + ch * 1024 * 64);
        int4* wd4 = (int4*)swc;
        for (int i = tid; i < 4096; i += 256) wd4[i] = ws4[i];
        for (int i = tid; i < 4096; i += 256) {
            int ill = i >> 10, kk = i & 1023;
            sxv[i] = g_actX[(size_t)(img0 + ill) * 8192 + ch * 1024 + kk];
        }
        __syncthreads();
        const float* xr = sxv + il * 1024;
        #pragma unroll 4
        for (int kk = 0; kk < 1024; ++kk) {
            float wv = __fmul_rn((float)swc[kk * 64 + o], sw);
            acc = fmaf(xr[kk], wv, acc);
        }
    }
    float y = __fadd_rn(acc, __ldg(&bias[o]));
    g_fc1[(size_t)(img0 + il) * 64 + o] = y;
    warp_amax_commit(fabsf(y), 6);
}

__global__ void __launch_bounds__(256) k_src(const float* __restrict__ x,
                                             const float* __restrict__ bias) {
    __shared__ float sw[64 * 64];
    const int tid = threadIdx.x;
    for (int i = tid; i < 4096; i += 256) sw[i] = g_wsrcv[i];
    __syncthreads();
    const int o = tid & 63, il = tid >> 6;
    const int img = blockIdx.x * 4 + il;
    const float* xr = x + (size_t)img * 64;
    float acc = 0.f;
    #pragma unroll 1
    for (int j = 0; j < 64; ++j)
        acc = fmaf(__ldg(&xr[j]), sw[j * 64 + o], acc);
    float y = __fadd_rn(acc, __ldg(&bias[o]));
    g_srcb[(size_t)img * 64 + o] = y;
    warp_amax_commit(fabsf(y), 7);
}

__global__ void k_merge() {
    int i = blockIdx.x * blockDim.x + threadIdx.x;
    if (i >= B_ * 64) return;
    float s6 = __fadd_rn(__fdiv_rn(__uint_as_float(g_amax[6]), 7.f), 1e-8f);
    float s7 = __fadd_rn(__fdiv_rn(__uint_as_float(g_amax[7]), 7.f), 1e-8f);
    float a = __fmul_rn(fminf(fmaxf(rintf(__fdiv_rn(g_fc1[i], s6)), -8.f), 7.f), s6);
    float c = __fmul_rn(fminf(fmaxf(rintf(__fdiv_rn(g_srcb[i], s7)), -8.f), 7.f), s7);
    g_merge[i] = __fadd_rn(a, c);
}

// same sequential FADD order as R8, loads batched 16-wide for MLP
__global__ void k_bnstats() {
    int c = threadIdx.x;                       // 64 threads
    float s = 0.f;
    for (int r0 = 0; r0 < B_; r0 += 16) {
        float v[16];
        #pragma unroll
        for (int j = 0; j < 16; j++) v[j] = g_merge[(r0 + j) * 64 + c];
        #pragma unroll
        for (int j = 0; j < 16; j++) s = __fadd_rn(s, v[j]);
    }
    float m = __fdiv_rn(s, 4096.f);
    g_mean[c] = m;
    float vv = 0.f;
    for (int r0 = 0; r0 < B_; r0 += 16) {
        float v[16];
        #pragma unroll
        for (int j = 0; j < 16; j++) v[j] = g_merge[(r0 + j) * 64 + c];
        #pragma unroll
        for (int j = 0; j < 16; j++) {
            float d = __fadd_rn(v[j], -m);
            vv = __fadd_rn(vv, __fmul_rn(d, d));
        }
    }
    g_var[c] = __fdiv_rn(vv, 4096.f);
}

__global__ void k_bnrelu(const float* __restrict__ gamma, const float* __restrict__ beta) {
    int i = blockIdx.x * blockDim.x + threadIdx.x;
    if (i >= B_ * 64) return;
    int c = i & 63;
    float ve = __fadd_rn(g_var[c], 1e-5f);
    float r1 = __fdiv_rn(1.0f, __fsqrt_rn(ve));
    float d  = __fadd_rn(g_merge[i], -g_mean[c]);
    float t  = __fadd_rn(__fmul_rn(__fmul_rn(gamma[c], d), r1), beta[c]);
    float r  = fmaxf(t, 0.0f);
    g_merge[i] = r;
    warp_amax_commit(r, 8);
}

__global__ void k_mq() {
    int i = blockIdx.x * blockDim.x + threadIdx.x;
    if (i >= B_ * 64) return;
    float s = __fadd_rn(__fdiv_rn(__uint_as_float(g_amax[8]), 15.f), 1e-8f);
    float q = fminf(fmaxf(rintf(__fdiv_rn(g_merge[i], s)), 0.f), 15.f);
    g_mq[i] = __fmul_rn(q, s);
}

__global__ void __launch_bounds__(256) k_out(const float* __restrict__ bias) {
    __shared__ float sw[64 * 64];
    const int tid = threadIdx.x;
    for (int i = tid; i < 4096; i += 256) sw[i] = g_woutv[i];
    __syncthreads();
    const int o = tid & 63, il = tid >> 6;
    const int img = blockIdx.x * 4 + il;
    const float* xr = g_mq + (size_t)img * 64;
    float acc = 0.f;
    #pragma unroll 1
    for (int j = 0; j < 64; ++j)
        acc = fmaf(xr[j], sw[j * 64 + o], acc);
    float y = __fadd_rn(acc, __ldg(&bias[o]));
    float t = xla_tanh(__fmul_rn(0.5f, y));
    float sig = __fadd_rn(__fmul_rn(0.5f, t), 0.5f);
    g_sig[(size_t)img * 64 + o] = sig;
    warp_amax_commit(sig, 9);
}

__global__ void k_final(float* __restrict__ out) {
    int i = blockIdx.x * blockDim.x + threadIdx.x;
    if (i >= B_ * 64) return;
    float s = __fadd_rn(__fdiv_rn(__uint_as_float(g_amax[9]), 15.f), 1e-8f);
    float q = fminf(fmaxf(rintf(__fdiv_rn(g_sig[i], s)), 0.f), 15.f);
    out[i] = __fmul_rn(q, s);
}

extern "C" void kernel_launch(void* const* d_in, const int* in_sizes, int n_in,
                              void* d_out, int out_size) {
    const float* cb    = (const float*)d_in[0];
    const float* srcx  = (const float*)d_in[1];
    const float* bconv[5] = {(const float*)d_in[3], (const float*)d_in[5],
                             (const float*)d_in[7], (const float*)d_in[9],
                             (const float*)d_in[11]};
    const float* wfc1  = (const float*)d_in[12];
    const float* bfc1  = (const float*)d_in[13];
    const float* wsrc  = (const float*)d_in[14];
    const float* bsrc  = (const float*)d_in[15];
    const float* gamma = (const float*)d_in[16];
    const float* beta  = (const float*)d_in[17];
    const float* wout  = (const float*)d_in[18];
    const float* bout  = (const float*)d_in[19];
    float* outp = (float*)d_out;

    WP wp;
    const int cins[5] = {12, 128, 128, 128, 128};
    for (int i = 0; i < 5; i++) {
        wp.w[i] = (const float*)d_in[2 + 2 * i];
        wp.cin[i] = cins[i];
        wp.n[i] = 128 * cins[i] * 9;
    }

    const int SMC128 = 128 * PIT * 2 * 4;      // 106496
    const int SMC16  = 16 * PIT * 2 * 4;       // 13312
    const int SMFC1  = 65536 + 16384;
    cudaFuncSetAttribute((const void*)k_conv<128>,
                         cudaFuncAttributeMaxDynamicSharedMemorySize, SMC128);
    cudaFuncSetAttribute((const void*)k_conv<16>,
                         cudaFuncAttributeMaxDynamicSharedMemorySize, SMC16);
    cudaFuncSetAttribute((const void*)k_fc1,
                         cudaFuncAttributeMaxDynamicSharedMemorySize, SMFC1);

    float* x0p = nullptr; float* xp = nullptr;
    uint2* entp = nullptr; int* ecp = nullptr;
    cudaGetSymbolAddress((void**)&x0p, g_actX0);
    cudaGetSymbolAddress((void**)&xp, g_actX);
    cudaGetSymbolAddress((void**)&entp, g_ent);
    cudaGetSymbolAddress((void**)&ecp, g_entcnt);

    k_zero_scalars<<<1, 32>>>();                          // 1
    k_amax_abs<<<2048, 256>>>(cb, B_ * 12 * 64, 0);       // 2
    k_prep0<<<(B_ * 16 * 64 + 255) / 256, 256>>>(cb);     // 3
    k_wsel5<<<5, 1024>>>(wp, 84 * 128);                   // 4
    k_went5<<<5, 128>>>(wp);                              // 5

    k_conv<16><<<B_ / 2, 256, SMC16>>>(x0p, bconv[0], entp, ecp, 1);      // 6 (ncu)
    for (int b = 1; b < 5; b++) {
        k_quantU<<<2048, 256>>>(b, 1);
        k_conv<128><<<B_ / 2, 256, SMC128>>>(xp, bconv[b],
                                             entp + (size_t)b * 128 * 1152,
                                             ecp + b * 128, b + 1);
    }
    k_quantU<<<2048, 256>>>(5, 0);

    k_wamax_lin<<<1, 1024>>>(wfc1, 64 * 8192, 5);
    k_wfc1c<<<(64 * 8192 + 255) / 256, 256>>>(wfc1);
    k_wlin_smallT<<<1, 1024>>>(wsrc, 0);
    k_wlin_smallT<<<1, 1024>>>(wout, 1);

    k_fc1<<<B_ / 4, 256, SMFC1>>>(bfc1);
    k_src<<<B_ / 4, 256>>>(srcx, bsrc);
    k_merge<<<(B_ * 64 + 255) / 256, 256>>>();
    k_bnstats<<<1, 64>>>();
    k_bnrelu<<<(B_ * 64 + 255) / 256, 256>>>(gamma, beta);
    k_mq<<<(B_ * 64 + 255) / 256, 256>>>();
    k_out<<<B_ / 4, 256>>>(bout);
    k_final<<<(B_ * 64 + 255) / 256, 256>>>(outp);
    (void)in_sizes; (void)n_in; (void)out_size;
}

// round 10
// speedup vs baseline: 1.3938x; 1.0582x over previous
#include <cuda_runtime.h>
#include <cstdint>

#define B_  4096

__device__ unsigned g_amax[16];
__device__ float    g_wscale[8];
__device__ float    g_wthr[8];
__device__ float    g_actX0[B_*16*64];
__device__ float    g_actX [B_*128*64];
__device__ float    g_actY [B_*128*64];
__device__ uint2    g_ent[5*128*1152];
__device__ int      g_entcnt[5*128];      // uint4-group count per co
__device__ float    g_wfc1v[8192*64];
__device__ float    g_wsrcv[64*64];
__device__ float    g_woutv[64*64];
__device__ float    g_fc1[B_*64];
__device__ float    g_srcb[B_*64];
__device__ float    g_merge[B_*64];
__device__ float    g_mq[B_*64];
__device__ float    g_sig[B_*64];
__device__ float    g_mean[64];
__device__ float    g_var[64];

struct WP { const float* w[5]; int n[5]; int cin[5]; };

__device__ __forceinline__ void warp_amax_commit(float v, int slot) {
    #pragma unroll
    for (int o = 16; o; o >>= 1) v = fmaxf(v, __shfl_xor_sync(0xffffffffu, v, o));
    if ((threadIdx.x & 31) == 0) atomicMax(&g_amax[slot], __float_as_uint(v));
}

__device__ __forceinline__ float xla_tanh(float x) {
    float ax = fabsf(x);
    float xc = fminf(fmaxf(x, -7.90531110763549805f), 7.90531110763549805f);
    float x2 = __fmul_rn(xc, xc);
    float p = -2.76076847742355e-16f;
    p = fmaf(p, x2, 2.00018790482477e-13f);
    p = fmaf(p, x2, -8.60467152213735e-11f);
    p = fmaf(p, x2, 5.12229709037114e-08f);
    p = fmaf(p, x2, 1.48572235717979e-05f);
    p = fmaf(p, x2, 6.37261928875436e-04f);
    p = fmaf(p, x2, 4.89352455891786e-03f);
    float num = __fmul_rn(xc, p);
    float q = 1.19825839466702e-06f;
    q = fmaf(q, x2, 1.18534705686654e-04f);
    q = fmaf(q, x2, 2.26843463243900e-03f);
    q = fmaf(q, x2, 4.89352518554385e-03f);
    float r = __fdiv_rn(num, q);
    return (ax < 0.0004f) ? x : r;
}

__global__ void k_zero_scalars() { if (threadIdx.x < 16) g_amax[threadIdx.x] = 0u; }

// 5 layers in parallel; warp-aggregated histogram atomics
__global__ void k_wsel5(WP wp, int keep) {
    const int L = blockIdx.x;
    const float* __restrict__ w = wp.w[L];
    const int n = wp.n[L];
    const int nr = (n + blockDim.x - 1) / blockDim.x * blockDim.x;
    __shared__ unsigned hist[256];
    __shared__ unsigned sh_prefix, sh_krem, sh_amax;
    const int tid = threadIdx.x;
    if (tid == 0) { sh_prefix = 0u; sh_krem = (unsigned)keep; sh_amax = 0u; }
    __syncthreads();
    unsigned mymax = 0u;
    for (int i = tid; i < n; i += blockDim.x)
        mymax = max(mymax, __float_as_uint(fabsf(w[i])));
    atomicMax(&sh_amax, mymax);
    __syncthreads();
    for (int shift = 24; shift >= 0; shift -= 8) {
        for (int j = tid; j < 256; j += blockDim.x) hist[j] = 0u;
        __syncthreads();
        const unsigned prefix = sh_prefix;
        for (int i = tid; i < nr; i += blockDim.x) {
            unsigned key = (i < n) ? __float_as_uint(fabsf(w[i])) : 0u;
            bool act = (i < n) && (shift == 24 || (key >> (shift + 8)) == prefix);
            unsigned am = __ballot_sync(0xffffffffu, act);
            if (act) {
                unsigned b = (key >> shift) & 255u;
                unsigned peers = __match_any_sync(am, b);
                if ((int)(threadIdx.x & 31) == __ffs(peers) - 1)
                    atomicAdd(&hist[b], (unsigned)__popc(peers));
            }
        }
        __syncthreads();
        if (tid == 0) {
            unsigned krem = sh_krem, cum = 0u; int d = 0;
            for (int b = 255; b >= 0; --b) {
                unsigned c = hist[b];
                if (cum + c >= krem) { d = b; sh_krem = krem - cum; break; }
                cum += c;
            }
            sh_prefix = (prefix << 8) | (unsigned)d;
        }
        __syncthreads();
    }
    if (tid == 0) {
        g_wthr[L]   = __uint_as_float(sh_prefix);
        g_wscale[L] = __fadd_rn(__fdiv_rn(__uint_as_float(sh_amax), 7.0f), 1e-8f);
    }
}

// sparse entries, (kh,kw,ci) ascending; u.x = byte offset into [row][ci][col] float4 tile
__global__ void k_went5(WP wp) {
    const int L = blockIdx.x, co = threadIdx.x;
    const float* __restrict__ w = wp.w[L];
    const int cin = wp.cin[L];
    const int cint = (cin <= 16) ? 16 : 128;      // tile ci count
    float thr = g_wthr[L], s = g_wscale[L];
    uint2* el = g_ent + ((size_t)L * 128 + co) * 1152;
    int n = 0;
    for (int kh = 0; kh < 3; ++kh)
        for (int kw = 0; kw < 3; ++kw)
            for (int ci = 0; ci < cin; ++ci) {
                float v = w[(co * cin + ci) * 9 + kh * 3 + kw];
                if (fabsf(v) >= thr) {
                    float q = fminf(fmaxf(rintf(__fdiv_rn(v, s)), -8.f), 7.f);
                    if (q != 0.f) {
                        el[n].x = (unsigned)((kh * cint * 10 + ci * 10 + kw) * 16);
                        el[n].y = __float_as_uint(__fmul_rn(q, s));
                        n++;
                    }
                }
            }
    if (n & 1) { el[n].x = 0u; el[n].y = 0u; n++; }   // fma(x,+0,acc)==acc exactly
    g_entcnt[L * 128 + co] = n >> 1;
}

__global__ void k_wamax_lin(const float* __restrict__ w, int n, int sidx) {
    __shared__ unsigned sm;
    if (threadIdx.x == 0) sm = 0u;
    __syncthreads();
    float m = 0.0f;
    for (int i = threadIdx.x; i < n; i += blockDim.x) m = fmaxf(m, fabsf(w[i]));
    atomicMax(&sm, __float_as_uint(m));
    __syncthreads();
    if (threadIdx.x == 0)
        g_wscale[sidx] = __fadd_rn(__fdiv_rn(__uint_as_float(sm), 7.0f), 1e-8f);
}

__global__ void k_wfc1v(const float* __restrict__ w) {
    int idx = blockIdx.x * blockDim.x + threadIdx.x;
    if (idx >= 64 * 8192) return;
    int o = idx >> 13, k = idx & 8191;
    float s = g_wscale[5];
    float q = fminf(fmaxf(rintf(__fdiv_rn(w[idx], s)), -8.f), 7.f);
    g_wfc1v[k * 64 + o] = __fmul_rn(q, s);
}

__global__ void k_wlin_smallT(const float* __restrict__ w, int which) {
    __shared__ unsigned sm;
    if (threadIdx.x == 0) sm = 0u;
    __syncthreads();
    float m = 0.0f;
    for (int i = threadIdx.x; i < 4096; i += blockDim.x) m = fmaxf(m, fabsf(w[i]));
    atomicMax(&sm, __float_as_uint(m));
    __syncthreads();
    float s = __fadd_rn(__fdiv_rn(__uint_as_float(sm), 7.0f), 1e-8f);
    float* dst = which ? g_woutv : g_wsrcv;
    for (int i = threadIdx.x; i < 4096; i += blockDim.x) {
        int o = i >> 6, j = i & 63;
        float q = fminf(fmaxf(rintf(__fdiv_rn(w[i], s)), -8.f), 7.f);
        dst[j * 64 + o] = __fmul_rn(q, s);
    }
}

__global__ void k_amax_abs(const float* __restrict__ x, int n, int slot) {
    float m = 0.0f;
    for (int i = blockIdx.x * blockDim.x + threadIdx.x; i < n; i += gridDim.x * blockDim.x)
        m = fmaxf(m, fabsf(x[i]));
    warp_amax_commit(m, slot);
}

__global__ void k_prep0(const float* __restrict__ cb) {
    int i = blockIdx.x * blockDim.x + threadIdx.x;
    if (i >= B_ * 16 * 64) return;
    int pix = i & 63, ci = (i >> 6) & 15, img = i >> 10;
    float xv = 0.f;
    if (ci < 12) {
        float s0 = __fadd_rn(__fdiv_rn(__uint_as_float(g_amax[0]), 7.0f), 1e-8f);
        float v = cb[(img * 12 + ci) * 64 + pix];
        float c = fminf(fmaxf(rintf(__fdiv_rn(v, s0)), -8.f), 7.f);
        xv = __fmul_rn(c, s0);
    }
    g_actX0[i] = xv;
}

__global__ void k_quantU(int slot, int mode) {
    float amax = __uint_as_float(g_amax[slot]);
    float su = __fadd_rn(__fdiv_rn(amax, 15.f), 1e-8f);
    float sx = 1.f;
    if (mode) {
        float mu = fminf(fmaxf(rintf(__fdiv_rn(amax, su)), 0.f), 15.f);
        sx = __fadd_rn(__fdiv_rn(__fmul_rn(mu, su), 7.f), 1e-8f);
    }
    const int n4 = B_ * 128 * 64 / 4;
    const float4* Y4 = (const float4*)g_actY;
    float4* X4 = (float4*)g_actX;
    for (int i = blockIdx.x * blockDim.x + threadIdx.x; i < n4; i += gridDim.x * blockDim.x) {
        float4 v = Y4[i], o;
        float* vp = &v.x; float* op = &o.x;
        #pragma unroll
        for (int j = 0; j < 4; j++) {
            float q = fminf(fmaxf(rintf(__fdiv_rn(vp[j], su)), 0.f), 15.f);
            float vq = __fmul_rn(q, su);
            float outv = vq;
            if (mode) {
                float c = fminf(fmaxf(rintf(__fdiv_rn(vq, sx)), -8.f), 7.f);
                outv = __fmul_rn(c, sx);
            }
            op[j] = outv;
        }
        X4[i] = o;
    }
}

// ---------------------------------------------------------------------------
// Conv: 4 images/CTA, float4 tile, layout [row][ci][col] (col stride 1 -> each
// 8-lane LDS.128 phase = 8 consecutive 16B slots = conflict-free wavefront).
// Per-output FMA order == entry order (Eigen sequential). 256 thr = 4 colanes
// x 2 warps x 32 lanes; warp rows {0,1,4,5}/{2,3,6,7}.
// ---------------------------------------------------------------------------
template<int CIN_T>
__global__ void __launch_bounds__(256) k_conv(const float* __restrict__ in,
                                              const float* __restrict__ bias,
                                              const uint2* __restrict__ ent,
                                              const int* __restrict__ ecnt,
                                              int outslot) {
    extern __shared__ float4 sT4[];            // 10 rows x CIN_T ci x 10 cols
    const int tid = threadIdx.x;
    const size_t imgA = (size_t)blockIdx.x * 4;
    constexpr int NV = CIN_T * 100;
    for (int i = tid; i < NV; i += 256) sT4[i] = make_float4(0.f, 0.f, 0.f, 0.f);
    __syncthreads();
    const float* iA = in + imgA * CIN_T * 64;
    const float* iB = iA + CIN_T * 64;
    const float* iC = iB + CIN_T * 64;
    const float* iD = iC + CIN_T * 64;
    for (int i = tid; i < CIN_T * 64; i += 256) {
        int ci = i >> 6, p = i & 63;
        int idx = ((p >> 3) + 1) * (CIN_T * 10) + ci * 10 + (p & 7) + 1;
        sT4[idx] = make_float4(iA[i], iB[i], iC[i], iD[i]);
    }
    __syncthreads();

    const int lane = tid & 31, w = (tid >> 5) & 1, colane = tid >> 6;
    const int rg = lane >> 3, c = lane & 7;
    const int r = rg + (rg & 2) + 2 * w;       // {0,1,4,5} or {2,3,6,7}
    const int pix = r * 8 + c;
    const char* base = (const char*)sT4 + (size_t)(r * CIN_T * 10 + c) * 16;
    float lmax = 0.f;

    #pragma unroll 1
    for (int it = 0; it < 32; ++it) {
        const int co = colane * 32 + it;
        const uint4* el = (const uint4*)(ent + (size_t)co * 1152);
        const int ng = ecnt[co];
        float a0 = 0.f, a1 = 0.f, a2 = 0.f, a3 = 0.f;
        #pragma unroll 2
        for (int g = 0; g < ng; ++g) {
            uint4 u = __ldg(&el[g]);
            float4 xa = *(const float4*)(base + u.x);
            float4 xb = *(const float4*)(base + u.z);
            float w0 = __uint_as_float(u.y), w1 = __uint_as_float(u.w);
            a0 = fmaf(xa.x, w0, a0); a1 = fmaf(xa.y, w0, a1);
            a2 = fmaf(xa.z, w0, a2); a3 = fmaf(xa.w, w0, a3);
            a0 = fmaf(xb.x, w1, a0); a1 = fmaf(xb.y, w1, a1);
            a2 = fmaf(xb.z, w1, a2); a3 = fmaf(xb.w, w1, a3);
        }
        float bv = __ldg(&bias[co]);
        float y0 = fmaxf(__fadd_rn(a0, bv), 0.f);
        float y1 = fmaxf(__fadd_rn(a1, bv), 0.f);
        float y2 = fmaxf(__fadd_rn(a2, bv), 0.f);
        float y3 = fmaxf(__fadd_rn(a3, bv), 0.f);
        lmax = fmaxf(lmax, fmaxf(fmaxf(y0, y1), fmaxf(y2, y3)));
        g_actY[((imgA + 0) * 128 + co) * 64 + pix] = y0;
        g_actY[((imgA + 1) * 128 + co) * 64 + pix] = y1;
        g_actY[((imgA + 2) * 128 + co) * 64 + pix] = y2;
        g_actY[((imgA + 3) * 128 + co) * 64 + pix] = y3;
    }
    warp_amax_commit(lmax, outslot);
}

// fc1: 8 images/CTA, f32 weight values staged in smem; sequential ascending k
__global__ void __launch_bounds__(256) k_fc1(const float* __restrict__ bias) {
    extern __shared__ float smf[];
    float* swf = smf;                          // [512][64]
    float* sxv = smf + 32768;                  // [8][512]
    const int tid = threadIdx.x;
    const int o = tid & 63, il = tid >> 6;     // il 0..3
    const size_t img0 = (size_t)blockIdx.x * 8;
    float acc0 = 0.f, acc1 = 0.f;
    #pragma unroll 1
    for (int ch = 0; ch < 16; ++ch) {
        __syncthreads();
        const float4* ws = (const float4*)(g_wfc1v + ch * 512 * 64);
        float4* wd = (float4*)swf;
        for (int i = tid; i < 8192; i += 256) wd[i] = ws[i];
        for (int i = tid; i < 4096; i += 256) {
            int ill = i >> 9, kk = i & 511;
            sxv[i] = g_actX[(img0 + ill) * 8192 + ch * 512 + kk];
        }
        __syncthreads();
        const float* xr0 = sxv + il * 512;
        const float* xr1 = sxv + (il + 4) * 512;
        #pragma unroll 4
        for (int kk = 0; kk < 512; ++kk) {
            float wv = swf[kk * 64 + o];
            acc0 = fmaf(xr0[kk], wv, acc0);
            acc1 = fmaf(xr1[kk], wv, acc1);
        }
    }
    float bv = __ldg(&bias[o]);
    float y0 = __fadd_rn(acc0, bv);
    float y1 = __fadd_rn(acc1, bv);
    g_fc1[(img0 + il) * 64 + o] = y0;
    g_fc1[(img0 + il + 4) * 64 + o] = y1;
    warp_amax_commit(fmaxf(fabsf(y0), fabsf(y1)), 6);
}

__global__ void __launch_bounds__(256) k_src(const float* __restrict__ x,
                                             const float* __restrict__ bias) {
    __shared__ float sw[64 * 64];
    const int tid = threadIdx.x;
    for (int i = tid; i < 4096; i += 256) sw[i] = g_wsrcv[i];
    __syncthreads();
    const int o = tid & 63, il = tid >> 6;
    const int img = blockIdx.x * 4 + il;
    const float* xr = x + (size_t)img * 64;
    float acc = 0.f;
    #pragma unroll 1
    for (int j = 0; j < 64; ++j)
        acc = fmaf(__ldg(&xr[j]), sw[j * 64 + o], acc);
    float y = __fadd_rn(acc, __ldg(&bias[o]));
    g_srcb[(size_t)img * 64 + o] = y;
    warp_amax_commit(fabsf(y), 7);
}

__global__ void k_merge() {
    int i = blockIdx.x * blockDim.x + threadIdx.x;
    if (i >= B_ * 64) return;
    float s6 = __fadd_rn(__fdiv_rn(__uint_as_float(g_amax[6]), 7.f), 1e-8f);
    float s7 = __fadd_rn(__fdiv_rn(__uint_as_float(g_amax[7]), 7.f), 1e-8f);
    float a = __fmul_rn(fminf(fmaxf(rintf(__fdiv_rn(g_fc1[i], s6)), -8.f), 7.f), s6);
    float c = __fmul_rn(fminf(fmaxf(rintf(__fdiv_rn(g_srcb[i], s7)), -8.f), 7.f), s7);
    g_merge[i] = __fadd_rn(a, c);
}

__global__ void k_bnstats() {
    int c = threadIdx.x;                       // 64 threads, sequential row order
    float s = 0.f;
    for (int r0 = 0; r0 < B_; r0 += 16) {
        float v[16];
        #pragma unroll
        for (int j = 0; j < 16; j++) v[j] = g_merge[(r0 + j) * 64 + c];
        #pragma unroll
        for (int j = 0; j < 16; j++) s = __fadd_rn(s, v[j]);
    }
    float m = __fdiv_rn(s, 4096.f);
    g_mean[c] = m;
    float vv = 0.f;
    for (int r0 = 0; r0 < B_; r0 += 16) {
        float v[16];
        #pragma unroll
        for (int j = 0; j < 16; j++) v[j] = g_merge[(r0 + j) * 64 + c];
        #pragma unroll
        for (int j = 0; j < 16; j++) {
            float d = __fadd_rn(v[j], -m);
            vv = __fadd_rn(vv, __fmul_rn(d, d));
        }
    }
    g_var[c] = __fdiv_rn(vv, 4096.f);
}

__global__ void k_bnrelu(const float* __restrict__ gamma, const float* __restrict__ beta) {
    int i = blockIdx.x * blockDim.x + threadIdx.x;
    if (i >= B_ * 64) return;
    int c = i & 63;
    float ve = __fadd_rn(g_var[c], 1e-5f);
    float r1 = __fdiv_rn(1.0f, __fsqrt_rn(ve));
    float d  = __fadd_rn(g_merge[i], -g_mean[c]);
    float t  = __fadd_rn(__fmul_rn(__fmul_rn(gamma[c], d), r1), beta[c]);
    float r  = fmaxf(t, 0.0f);
    g_merge[i] = r;
    warp_amax_commit(r, 8);
}

__global__ void k_mq() {
    int i = blockIdx.x * blockDim.x + threadIdx.x;
    if (i >= B_ * 64) return;
    float s = __fadd_rn(__fdiv_rn(__uint_as_float(g_amax[8]), 15.f), 1e-8f);
    float q = fminf(fmaxf(rintf(__fdiv_rn(g_merge[i], s)), 0.f), 15.f);
    g_mq[i] = __fmul_rn(q, s);
}

__global__ void __launch_bounds__(256) k_out(const float* __restrict__ bias) {
    __shared__ float sw[64 * 64];
    const int tid = threadIdx.x;
    for (int i = tid; i < 4096; i += 256) sw[i] = g_woutv[i];
    __syncthreads();
    const int o = tid & 63, il = tid >> 6;
    const int img = blockIdx.x * 4 + il;
    const float* xr = g_mq + (size_t)img * 64;
    float acc = 0.f;
    #pragma unroll 1
    for (int j = 0; j < 64; ++j)
        acc = fmaf(xr[j], sw[j * 64 + o], acc);
    float y = __fadd_rn(acc, __ldg(&bias[o]));
    float t = xla_tanh(__fmul_rn(0.5f, y));
    float sig = __fadd_rn(__fmul_rn(0.5f, t), 0.5f);
    g_sig[(size_t)img * 64 + o] = sig;
    warp_amax_commit(sig, 9);
}

__global__ void k_final(float* __restrict__ out) {
    int i = blockIdx.x * blockDim.x + threadIdx.x;
    if (i >= B_ * 64) return;
    float s = __fadd_rn(__fdiv_rn(__uint_as_float(g_amax[9]), 15.f), 1e-8f);
    float q = fminf(fmaxf(rintf(__fdiv_rn(g_sig[i], s)), 0.f), 15.f);
    out[i] = __fmul_rn(q, s);
}

extern "C" void kernel_launch(void* const* d_in, const int* in_sizes, int n_in,
                              void* d_out, int out_size) {
    const float* cb    = (const float*)d_in[0];
    const float* srcx  = (const float*)d_in[1];
    const float* bconv[5] = {(const float*)d_in[3], (const float*)d_in[5],
                             (const float*)d_in[7], (const float*)d_in[9],
                             (const float*)d_in[11]};
    const float* wfc1  = (const float*)d_in[12];
    const float* bfc1  = (const float*)d_in[13];
    const float* wsrc  = (const float*)d_in[14];
    const float* bsrc  = (const float*)d_in[15];
    const float* gamma = (const float*)d_in[16];
    const float* beta  = (const float*)d_in[17];
    const float* wout  = (const float*)d_in[18];
    const float* bout  = (const float*)d_in[19];
    float* outp = (float*)d_out;

    WP wp;
    const int cins[5] = {12, 128, 128, 128, 128};
    for (int i = 0; i < 5; i++) {
        wp.w[i] = (const float*)d_in[2 + 2 * i];
        wp.cin[i] = cins[i];
        wp.n[i] = 128 * cins[i] * 9;
    }

    const int SMC128 = 128 * 100 * 16;         // 204800
    const int SMC16  = 16 * 100 * 16;          // 25600
    const int SMFC1  = (32768 + 4096) * 4;     // 147456
    cudaFuncSetAttribute((const void*)k_conv<128>,
                         cudaFuncAttributeMaxDynamicSharedMemorySize, SMC128);
    cudaFuncSetAttribute((const void*)k_conv<16>,
                         cudaFuncAttributeMaxDynamicSharedMemorySize, SMC16);
    cudaFuncSetAttribute((const void*)k_fc1,
                         cudaFuncAttributeMaxDynamicSharedMemorySize, SMFC1);

    float* x0p = nullptr; float* xp = nullptr;
    uint2* entp = nullptr; int* ecp = nullptr;
    cudaGetSymbolAddress((void**)&x0p, g_actX0);
    cudaGetSymbolAddress((void**)&xp, g_actX);
    cudaGetSymbolAddress((void**)&entp, g_ent);
    cudaGetSymbolAddress((void**)&ecp, g_entcnt);

    k_zero_scalars<<<1, 32>>>();
    k_amax_abs<<<2048, 256>>>(cb, B_ * 12 * 64, 0);
    k_prep0<<<(B_ * 16 * 64 + 255) / 256, 256>>>(cb);
    k_wsel5<<<5, 1024>>>(wp, 84 * 128);
    k_went5<<<5, 128>>>(wp);
    k_wamax_lin<<<1, 1024>>>(wfc1, 64 * 8192, 5);
    k_wfc1v<<<(64 * 8192 + 255) / 256, 256>>>(wfc1);
    k_wlin_smallT<<<1, 1024>>>(wsrc, 0);
    k_wlin_smallT<<<1, 1024>>>(wout, 1);

    k_conv<16><<<B_ / 4, 256, SMC16>>>(x0p, bconv[0], entp, ecp, 1);
    for (int b = 1; b < 5; b++) {
        k_quantU<<<2048, 256>>>(b, 1);
        k_conv<128><<<B_ / 4, 256, SMC128>>>(xp, bconv[b],
                                             entp + (size_t)b * 128 * 1152,
                                             ecp + b * 128, b + 1);
    }
    k_quantU<<<2048, 256>>>(5, 0);

    k_fc1<<<B_ / 8, 256, SMFC1>>>(bfc1);
    k_src<<<B_ / 4, 256>>>(srcx, bsrc);
    k_merge<<<(B_ * 64 + 255) / 256, 256>>>();
    k_bnstats<<<1, 64>>>();
    k_bnrelu<<<(B_ * 64 + 255) / 256, 256>>>(gamma, beta);
    k_mq<<<(B_ * 64 + 255) / 256, 256>>>();
    k_out<<<B_ / 4, 256>>>(bout);
    k_final<<<(B_ * 64 + 255) / 256, 256>>>(outp);
    (void)in_sizes; (void)n_in; (void)out_size;
}

// round 11
// speedup vs baseline: 2.2092x; 1.5850x over previous
#include <cuda_runtime.h>
#include <cstdint>

#define B_  4096

__device__ unsigned g_amax[16];
__device__ float    g_wscale[8];
__device__ float    g_wthr[8];
__device__ float    g_actY [B_*128*64];
__device__ uint2    g_ent[5*128*1152];
__device__ int      g_entcnt[5*128];
__device__ float    g_wfc1v[8192*64];
__device__ float    g_wsrcv[64*64];
__device__ float    g_woutv[64*64];
__device__ float    g_fc1[B_*64];
__device__ float    g_srcb[B_*64];
__device__ float    g_merge[B_*64];
__device__ float    g_sig[B_*64];
__device__ float    g_mean[64];
__device__ float    g_var[64];

struct WP { const float* w[5]; int n[5]; int cin[5];
            const float* wfc1; const float* wsrc; const float* wout; };

__device__ __forceinline__ void warp_amax_commit(float v, int slot) {
    #pragma unroll
    for (int o = 16; o; o >>= 1) v = fmaxf(v, __shfl_xor_sync(0xffffffffu, v, o));
    if ((threadIdx.x & 31) == 0) atomicMax(&g_amax[slot], __float_as_uint(v));
}

__device__ __forceinline__ float xla_tanh(float x) {
    float ax = fabsf(x);
    float xc = fminf(fmaxf(x, -7.90531110763549805f), 7.90531110763549805f);
    float x2 = __fmul_rn(xc, xc);
    float p = -2.76076847742355e-16f;
    p = fmaf(p, x2, 2.00018790482477e-13f);
    p = fmaf(p, x2, -8.60467152213735e-11f);
    p = fmaf(p, x2, 5.12229709037114e-08f);
    p = fmaf(p, x2, 1.48572235717979e-05f);
    p = fmaf(p, x2, 6.37261928875436e-04f);
    p = fmaf(p, x2, 4.89352455891786e-03f);
    float num = __fmul_rn(xc, p);
    float q = 1.19825839466702e-06f;
    q = fmaf(q, x2, 1.18534705686654e-04f);
    q = fmaf(q, x2, 2.26843463243900e-03f);
    q = fmaf(q, x2, 4.89352518554385e-03f);
    float r = __fdiv_rn(num, q);
    return (ax < 0.0004f) ? x : r;
}

__global__ void k_zero16() { if (threadIdx.x < 16) g_amax[threadIdx.x] = 0u; }

__global__ void k_amax_cb(const float* __restrict__ x, int n) {
    float m = 0.0f;
    for (int i = blockIdx.x * blockDim.x + threadIdx.x; i < n; i += gridDim.x * blockDim.x)
        m = fmaxf(m, fabsf(x[i]));
    warp_amax_commit(m, 0);
}

// 8 blocks: 0-4 conv wsel+entries, 5 fc1 amax, 6 src quantT, 7 out quantT
__global__ void __launch_bounds__(1024) k_wprep(WP wp, int keep) {
    const int L = blockIdx.x;
    const int tid = threadIdx.x;
    if (L < 5) {
        const float* __restrict__ w = wp.w[L];
        const int n = wp.n[L];
        __shared__ unsigned hist[256];
        __shared__ unsigned sh_prefix, sh_krem, sh_amax;
        __shared__ float s_thr, s_s;
        if (tid == 0) { sh_prefix = 0u; sh_krem = (unsigned)keep; sh_amax = 0u; }
        __syncthreads();
        unsigned mymax = 0u;
        for (int i = tid; i < n; i += blockDim.x)
            mymax = max(mymax, __float_as_uint(fabsf(w[i])));
        atomicMax(&sh_amax, mymax);
        __syncthreads();
        for (int shift = 24; shift >= 0; shift -= 8) {
            for (int j = tid; j < 256; j += blockDim.x) hist[j] = 0u;
            __syncthreads();
            const unsigned prefix = sh_prefix;
            for (int i = tid; i < n; i += blockDim.x) {
                unsigned key = __float_as_uint(fabsf(w[i]));
                if (shift == 24 || (key >> (shift + 8)) == prefix)
                    atomicAdd(&hist[(key >> shift) & 255u], 1u);
            }
            __syncthreads();
            if (tid == 0) {
                unsigned krem = sh_krem, cum = 0u; int d = 0;
                for (int b = 255; b >= 0; --b) {
                    unsigned c = hist[b];
                    if (cum + c >= krem) { d = b; sh_krem = krem - cum; break; }
                    cum += c;
                }
                sh_prefix = (prefix << 8) | (unsigned)d;
            }
            __syncthreads();
        }
        if (tid == 0) {
            s_thr = __uint_as_float(sh_prefix);
            s_s   = __fadd_rn(__fdiv_rn(__uint_as_float(sh_amax), 7.0f), 1e-8f);
            g_wthr[L] = s_thr;
            g_wscale[L] = s_s;
        }
        __syncthreads();
        if (tid < 128) {
            const int co = tid, cin = wp.cin[L];
            const int cint = (cin <= 16) ? 16 : 128;
            float thr = s_thr, s = s_s;
            uint2* el = g_ent + ((size_t)L * 128 + co) * 1152;
            int m = 0;
            for (int kh = 0; kh < 3; ++kh)
                for (int kw = 0; kw < 3; ++kw)
                    for (int ci = 0; ci < cin; ++ci) {
                        float v = w[(co * cin + ci) * 9 + kh * 3 + kw];
                        if (fabsf(v) >= thr) {
                            float q = fminf(fmaxf(rintf(__fdiv_rn(v, s)), -8.f), 7.f);
                            if (q != 0.f) {
                                el[m].x = (unsigned)((kh * cint * 10 + ci * 10 + kw) * 16);
                                el[m].y = __float_as_uint(__fmul_rn(q, s));
                                m++;
                            }
                        }
                    }
            if (m & 1) { el[m].x = 0u; el[m].y = 0u; m++; }
            g_entcnt[L * 128 + co] = m >> 1;
        }
    } else {
        __shared__ unsigned sm;
        const float* w = (L == 5) ? wp.wfc1 : (L == 6 ? wp.wsrc : wp.wout);
        const int n = (L == 5) ? 64 * 8192 : 4096;
        if (tid == 0) sm = 0u;
        __syncthreads();
        float m = 0.0f;
        for (int i = tid; i < n; i += blockDim.x) m = fmaxf(m, fabsf(w[i]));
        atomicMax(&sm, __float_as_uint(m));
        __syncthreads();
        float s = __fadd_rn(__fdiv_rn(__uint_as_float(sm), 7.0f), 1e-8f);
        if (L == 5) { if (tid == 0) g_wscale[5] = s; return; }
        float* dst = (L == 7) ? g_woutv : g_wsrcv;
        for (int i = tid; i < 4096; i += blockDim.x) {
            int o = i >> 6, j = i & 63;
            float q = fminf(fmaxf(rintf(__fdiv_rn(w[i], s)), -8.f), 7.f);
            dst[j * 64 + o] = __fmul_rn(q, s);
        }
    }
}

__global__ void k_wfc1v(const float* __restrict__ w) {
    int idx = blockIdx.x * blockDim.x + threadIdx.x;
    if (idx >= 64 * 8192) return;
    int o = idx >> 13, k = idx & 8191;
    float s = g_wscale[5];
    float q = fminf(fmaxf(rintf(__fdiv_rn(w[idx], s)), -8.f), 7.f);
    g_wfc1v[k * 64 + o] = __fmul_rn(q, s);
}

// ---------------------------------------------------------------------------
// Conv: 4 images/CTA, float4 tile [row][ci][col] (conflict-free LDS.128).
// MODE 0: quantize chessboard on load (in = cb, slot 0).
// MODE 1: read g_actY directly, qrelu-quant + fq_signed-quant on load.
// Per-output FMA order == entry order (Eigen sequential, proven invariant).
// ---------------------------------------------------------------------------
template<int CIN_T, int MODE, int NTHR>
__global__ void __launch_bounds__(1024) k_conv(const float* __restrict__ in,
                                               const float* __restrict__ bias,
                                               const uint2* __restrict__ ent,
                                               const int* __restrict__ ecnt,
                                               int inslot, int outslot) {
    extern __shared__ float4 sT4[];
    const int tid = threadIdx.x;
    const size_t imgA = (size_t)blockIdx.x * 4;
    for (int i = tid; i < CIN_T * 100; i += NTHR) sT4[i] = make_float4(0.f, 0.f, 0.f, 0.f);
    __syncthreads();

    float su, sx = 1.f;
    if (MODE == 0) {
        su = __fadd_rn(__fdiv_rn(__uint_as_float(g_amax[0]), 7.0f), 1e-8f);
    } else {
        float amax = __uint_as_float(g_amax[inslot]);
        su = __fadd_rn(__fdiv_rn(amax, 15.f), 1e-8f);
        float mu = fminf(fmaxf(rintf(__fdiv_rn(amax, su)), 0.f), 15.f);
        sx = __fadd_rn(__fdiv_rn(__fmul_rn(mu, su), 7.f), 1e-8f);
    }
    for (int i = tid; i < CIN_T * 64; i += NTHR) {
        int ci = i >> 6, p = i & 63;
        float4 v = make_float4(0.f, 0.f, 0.f, 0.f);
        float* vp = &v.x;
        if (MODE == 0) {
            if (ci < 12) {
                #pragma unroll
                for (int k = 0; k < 4; k++) {
                    float raw = in[((imgA + k) * 12 + ci) * 64 + p];
                    float c = fminf(fmaxf(rintf(__fdiv_rn(raw, su)), -8.f), 7.f);
                    vp[k] = __fmul_rn(c, su);
                }
            }
        } else {
            #pragma unroll
            for (int k = 0; k < 4; k++) {
                float raw = g_actY[((imgA + k) * 128 + ci) * 64 + p];
                float q = fminf(fmaxf(rintf(__fdiv_rn(raw, su)), 0.f), 15.f);
                float vq = __fmul_rn(q, su);
                float c = fminf(fmaxf(rintf(__fdiv_rn(vq, sx)), -8.f), 7.f);
                vp[k] = __fmul_rn(c, sx);
            }
        }
        sT4[((p >> 3) + 1) * (CIN_T * 10) + ci * 10 + (p & 7) + 1] = v;
    }
    __syncthreads();

    const int lane = tid & 31, w = (tid >> 5) & 1, colane = tid >> 6;
    constexpr int NCO = 128 / (NTHR / 64);
    const int rg = lane >> 3, c = lane & 7;
    const int r = rg + (rg & 2) + 2 * w;
    const int pix = r * 8 + c;
    const char* base = (const char*)sT4 + (size_t)(r * CIN_T * 10 + c) * 16;
    float lmax = 0.f;

    #pragma unroll 1
    for (int it = 0; it < NCO; ++it) {
        const int co = colane * NCO + it;
        const uint4* el = (const uint4*)(ent + (size_t)co * 1152);
        const int ng = ecnt[co];
        float a0 = 0.f, a1 = 0.f, a2 = 0.f, a3 = 0.f;
        #pragma unroll 2
        for (int g = 0; g < ng; ++g) {
            uint4 u = __ldg(&el[g]);
            float4 xa = *(const float4*)(base + u.x);
            float4 xb = *(const float4*)(base + u.z);
            float w0 = __uint_as_float(u.y), w1 = __uint_as_float(u.w);
            a0 = fmaf(xa.x, w0, a0); a1 = fmaf(xa.y, w0, a1);
            a2 = fmaf(xa.z, w0, a2); a3 = fmaf(xa.w, w0, a3);
            a0 = fmaf(xb.x, w1, a0); a1 = fmaf(xb.y, w1, a1);
            a2 = fmaf(xb.z, w1, a2); a3 = fmaf(xb.w, w1, a3);
        }
        float bv = __ldg(&bias[co]);
        float y0 = fmaxf(__fadd_rn(a0, bv), 0.f);
        float y1 = fmaxf(__fadd_rn(a1, bv), 0.f);
        float y2 = fmaxf(__fadd_rn(a2, bv), 0.f);
        float y3 = fmaxf(__fadd_rn(a3, bv), 0.f);
        lmax = fmaxf(lmax, fmaxf(fmaxf(y0, y1), fmaxf(y2, y3)));
        g_actY[((imgA + 0) * 128 + co) * 64 + pix] = y0;
        g_actY[((imgA + 1) * 128 + co) * 64 + pix] = y1;
        g_actY[((imgA + 2) * 128 + co) * 64 + pix] = y2;
        g_actY[((imgA + 3) * 128 + co) * 64 + pix] = y3;
    }
    warp_amax_commit(lmax, outslot);
}

// NOTE: MODE 1 writes g_actY in-place while reading it.  Safe because each CTA
// reads ONLY its own 4 images' activations and writes ONLY those same images,
// and all reads complete (into smem, __syncthreads) before any write.

// fc1: 8 images/CTA, qrelu-quant fused into x load (slot 5), ascending k
__global__ void __launch_bounds__(256) k_fc1(const float* __restrict__ bias) {
    extern __shared__ float smf[];
    float* swf = smf;
    float* sxv = smf + 32768;
    const int tid = threadIdx.x;
    const int o = tid & 63, il = tid >> 6;
    const size_t img0 = (size_t)blockIdx.x * 8;
    const float su = __fadd_rn(__fdiv_rn(__uint_as_float(g_amax[5]), 15.f), 1e-8f);
    float acc0 = 0.f, acc1 = 0.f;
    #pragma unroll 1
    for (int ch = 0; ch < 16; ++ch) {
        __syncthreads();
        const float4* ws = (const float4*)(g_wfc1v + ch * 512 * 64);
        float4* wd = (float4*)swf;
        for (int i = tid; i < 8192; i += 256) wd[i] = ws[i];
        for (int i = tid; i < 4096; i += 256) {
            int ill = i >> 9, kk = i & 511;
            float raw = g_actY[(img0 + ill) * 8192 + ch * 512 + kk];
            float q = fminf(fmaxf(rintf(__fdiv_rn(raw, su)), 0.f), 15.f);
            sxv[i] = __fmul_rn(q, su);
        }
        __syncthreads();
        const float* xr0 = sxv + il * 512;
        const float* xr1 = sxv + (il + 4) * 512;
        #pragma unroll 4
        for (int kk = 0; kk < 512; ++kk) {
            float wv = swf[kk * 64 + o];
            acc0 = fmaf(xr0[kk], wv, acc0);
            acc1 = fmaf(xr1[kk], wv, acc1);
        }
    }
    float bv = __ldg(&bias[o]);
    float y0 = __fadd_rn(acc0, bv);
    float y1 = __fadd_rn(acc1, bv);
    g_fc1[(img0 + il) * 64 + o] = y0;
    g_fc1[(img0 + il + 4) * 64 + o] = y1;
    warp_amax_commit(fmaxf(fabsf(y0), fabsf(y1)), 6);
}

__global__ void __launch_bounds__(256) k_src(const float* __restrict__ x,
                                             const float* __restrict__ bias) {
    __shared__ float sw[64 * 64];
    const int tid = threadIdx.x;
    for (int i = tid; i < 4096; i += 256) sw[i] = g_wsrcv[i];
    __syncthreads();
    const int o = tid & 63, il = tid >> 6;
    const int img = blockIdx.x * 4 + il;
    const float* xr = x + (size_t)img * 64;
    float acc = 0.f;
    #pragma unroll 1
    for (int j = 0; j < 64; ++j)
        acc = fmaf(__ldg(&xr[j]), sw[j * 64 + o], acc);
    float y = __fadd_rn(acc, __ldg(&bias[o]));
    g_srcb[(size_t)img * 64 + o] = y;
    warp_amax_commit(fabsf(y), 7);
}

__global__ void k_merge() {
    int i = blockIdx.x * blockDim.x + threadIdx.x;
    if (i >= B_ * 64) return;
    float s6 = __fadd_rn(__fdiv_rn(__uint_as_float(g_amax[6]), 7.f), 1e-8f);
    float s7 = __fadd_rn(__fdiv_rn(__uint_as_float(g_amax[7]), 7.f), 1e-8f);
    float a = __fmul_rn(fminf(fmaxf(rintf(__fdiv_rn(g_fc1[i], s6)), -8.f), 7.f), s6);
    float c = __fmul_rn(fminf(fmaxf(rintf(__fdiv_rn(g_srcb[i], s7)), -8.f), 7.f), s7);
    g_merge[i] = __fadd_rn(a, c);
}

__global__ void k_bnstats() {
    int c = threadIdx.x;
    float s = 0.f;
    for (int r0 = 0; r0 < B_; r0 += 16) {
        float v[16];
        #pragma unroll
        for (int j = 0; j < 16; j++) v[j] = g_merge[(r0 + j) * 64 + c];
        #pragma unroll
        for (int j = 0; j < 16; j++) s = __fadd_rn(s, v[j]);
    }
    float m = __fdiv_rn(s, 4096.f);
    g_mean[c] = m;
    float vv = 0.f;
    for (int r0 = 0; r0 < B_; r0 += 16) {
        float v[16];
        #pragma unroll
        for (int j = 0; j < 16; j++) v[j] = g_merge[(r0 + j) * 64 + c];
        #pragma unroll
        for (int j = 0; j < 16; j++) {
            float d = __fadd_rn(v[j], -m);
            vv = __fadd_rn(vv, __fmul_rn(d, d));
        }
    }
    g_var[c] = __fdiv_rn(vv, 4096.f);
}

__global__ void k_bnrelu(const float* __restrict__ gamma, const float* __restrict__ beta) {
    int i = blockIdx.x * blockDim.x + threadIdx.x;
    if (i >= B_ * 64) return;
    int c = i & 63;
    float ve = __fadd_rn(g_var[c], 1e-5f);
    float r1 = __fdiv_rn(1.0f, __fsqrt_rn(ve));
    float d  = __fadd_rn(g_merge[i], -g_mean[c]);
    float t  = __fadd_rn(__fmul_rn(__fmul_rn(gamma[c], d), r1), beta[c]);
    float r  = fmaxf(t, 0.0f);
    g_merge[i] = r;
    warp_amax_commit(r, 8);
}

__global__ void __launch_bounds__(256) k_out(const float* __restrict__ bias) {
    __shared__ float sw[64 * 64];
    __shared__ float sx[256];
    const int tid = threadIdx.x;
    for (int i = tid; i < 4096; i += 256) sw[i] = g_woutv[i];
    const float s8 = __fadd_rn(__fdiv_rn(__uint_as_float(g_amax[8]), 15.f), 1e-8f);
    {
        int img_l = tid >> 6, j = tid & 63;
        float mv = g_merge[((size_t)blockIdx.x * 4 + img_l) * 64 + j];
        float q = fminf(fmaxf(rintf(__fdiv_rn(mv, s8)), 0.f), 15.f);
        sx[tid] = __fmul_rn(q, s8);
    }
    __syncthreads();
    const int o = tid & 63, il = tid >> 6;
    const float* xr = sx + il * 64;
    float acc = 0.f;
    #pragma unroll 1
    for (int j = 0; j < 64; ++j)
        acc = fmaf(xr[j], sw[j * 64 + o], acc);
    float y = __fadd_rn(acc, __ldg(&bias[o]));
    float t = xla_tanh(__fmul_rn(0.5f, y));
    float sig = __fadd_rn(__fmul_rn(0.5f, t), 0.5f);
    g_sig[((size_t)blockIdx.x * 4 + il) * 64 + o] = sig;
    warp_amax_commit(sig, 9);
}

__global__ void k_final(float* __restrict__ out) {
    int i = blockIdx.x * blockDim.x + threadIdx.x;
    if (i >= B_ * 64) return;
    float s = __fadd_rn(__fdiv_rn(__uint_as_float(g_amax[9]), 15.f), 1e-8f);
    float q = fminf(fmaxf(rintf(__fdiv_rn(g_sig[i], s)), 0.f), 15.f);
    out[i] = __fmul_rn(q, s);
}

extern "C" void kernel_launch(void* const* d_in, const int* in_sizes, int n_in,
                              void* d_out, int out_size) {
    const float* cb    = (const float*)d_in[0];
    const float* srcx  = (const float*)d_in[1];
    const float* bconv[5] = {(const float*)d_in[3], (const float*)d_in[5],
                             (const float*)d_in[7], (const float*)d_in[9],
                             (const float*)d_in[11]};
    const float* wfc1  = (const float*)d_in[12];
    const float* bfc1  = (const float*)d_in[13];
    const float* gamma = (const float*)d_in[16];
    const float* beta  = (const float*)d_in[17];
    const float* bout  = (const float*)d_in[19];
    float* outp = (float*)d_out;

    WP wp;
    const int cins[5] = {12, 128, 128, 128, 128};
    for (int i = 0; i < 5; i++) {
        wp.w[i] = (const float*)d_in[2 + 2 * i];
        wp.cin[i] = cins[i];
        wp.n[i] = 128 * cins[i] * 9;
    }
    wp.wfc1 = wfc1;
    wp.wsrc = (const float*)d_in[14];
    wp.wout = (const float*)d_in[18];

    const int SMC128 = 128 * 100 * 16;         // 204800
    const int SMC16  = 16 * 100 * 16;          // 25600
    const int SMFC1  = (32768 + 4096) * 4;     // 147456
    cudaFuncSetAttribute((const void*)k_conv<128, 1, 1024>,
                         cudaFuncAttributeMaxDynamicSharedMemorySize, SMC128);
    cudaFuncSetAttribute((const void*)k_conv<16, 0, 256>,
                         cudaFuncAttributeMaxDynamicSharedMemorySize, SMC16);
    cudaFuncSetAttribute((const void*)k_fc1,
                         cudaFuncAttributeMaxDynamicSharedMemorySize, SMFC1);

    uint2* entp = nullptr; int* ecp = nullptr;
    cudaGetSymbolAddress((void**)&entp, g_ent);
    cudaGetSymbolAddress((void**)&ecp, g_entcnt);

    k_zero16<<<1, 32>>>();
    k_amax_cb<<<1024, 256>>>(cb, B_ * 12 * 64);
    k_wprep<<<8, 1024>>>(wp, 84 * 128);
    k_conv<16, 0, 256><<<B_ / 4, 256, SMC16>>>(cb, bconv[0], entp, ecp, 0, 1);
    for (int b = 1; b < 5; b++)                 // first iteration = ncu capture slot
        k_conv<128, 1, 1024><<<B_ / 4, 1024, SMC128>>>(
            cb /*unused in MODE1*/, bconv[b],
            entp + (size_t)b * 128 * 1152, ecp + b * 128, b, b + 1);
    k_wfc1v<<<(64 * 8192 + 255) / 256, 256>>>(wfc1);
    k_fc1<<<B_ / 8, 256, SMFC1>>>(bfc1);
    k_src<<<B_ / 4, 256>>>(srcx, (const float*)d_in[15]);
    k_merge<<<(B_ * 64 + 255) / 256, 256>>>();
    k_bnstats<<<1, 64>>>();
    k_bnrelu<<<(B_ * 64 + 255) / 256, 256>>>(gamma, beta);
    k_out<<<B_ / 4, 256>>>(bout);
    k_final<<<(B_ * 64 + 255) / 256, 256>>>(outp);
    (void)in_sizes; (void)n_in; (void)out_size;
}